// round 2
// baseline (speedup 1.0000x reference)
#include <cuda_runtime.h>

// Problem constants
#define B_      16
#define R_      2
#define ROWS    32          // B_*R_
#define OUTN    1024
#define LUTN    64
#define LUTK    6
#define ENT     64          // 1 << LUTK
#define FEAT    384         // LUTN * LUTK
#define WQ_PITCH 68         // 64 + 4 pad: avoids bank-aligned LDS conflicts across rows

#define NTHREADS 256
#define SMEM_X_FLOATS   (ROWS * FEAT)            // 12288
#define SMEM_WQ_FLOATS  (LUTN * WQ_PITCH)        // 4352
#define SMEM_BYTES      ((SMEM_X_FLOATS + SMEM_WQ_FLOATS) * 4)  // 66560

__global__ __launch_bounds__(NTHREADS, 2)
void lut_tree_kernel(const float* __restrict__ x,
                     const float* __restrict__ w,
                     float* __restrict__ out)
{
    extern __shared__ float smem[];
    float* s_x  = smem;                  // [ROWS][FEAT]
    float* s_wq = smem + SMEM_X_FLOATS;  // [LUTN][WQ_PITCH]

    const int o   = blockIdx.x;          // output-feature index, 0..1023
    const int tid = threadIdx.x;

    // ---- Stage x rows for this `o`: 32 rows x 384 floats, float4 coalesced ----
    {
        const float4* xg = reinterpret_cast<const float4*>(x);
        const int n4 = ROWS * FEAT / 4;              // 3072
        #pragma unroll
        for (int i = tid; i < n4; i += NTHREADS) {
            const int row = i / (FEAT / 4);
            const int v   = i - row * (FEAT / 4);
            float4 val = xg[(size_t)(row * OUTN + o) * (FEAT / 4) + v];
            reinterpret_cast<float4*>(s_x + row * FEAT)[v] = val;
        }
    }

    // ---- Stage w[o] and soft-quantize once: wq = (tanh(w)+1)/2 ----
    {
        const float4* wg = reinterpret_cast<const float4*>(w + (size_t)o * LUTN * ENT);
        const int n4 = LUTN * ENT / 4;               // 1024
        #pragma unroll
        for (int i = tid; i < n4; i += NTHREADS) {
            float4 val = wg[i];
            const int lut = i >> 4;                  // (i*4)/64
            const int e   = (i << 2) & (ENT - 1);
            float* dst = s_wq + lut * WQ_PITCH + e;  // 16B aligned
            float4 q;
            q.x = (tanhf(val.x) + 1.0f) * 0.5f;
            q.y = (tanhf(val.y) + 1.0f) * 0.5f;
            q.z = (tanhf(val.z) + 1.0f) * 0.5f;
            q.w = (tanhf(val.w) + 1.0f) * 0.5f;
            *reinterpret_cast<float4*>(dst) = q;
        }
    }
    __syncthreads();

    // ---- Thread = (lut, rowgroup). 64 luts x 4 rowgroups of 8 rows each. ----
    const int lut = tid & (LUTN - 1);
    const int rg  = tid >> 6;

    // Level-0 table in registers, hoisted across the 8 rows:
    // base[j] = wq[2j], d0[j] = wq[2j+1]-wq[2j]
    float base[32], d0[32];
    {
        const float* wqrow = s_wq + lut * WQ_PITCH;
        #pragma unroll
        for (int j = 0; j < 32; ++j) {
            const float a = wqrow[2 * j];
            const float b = wqrow[2 * j + 1];
            base[j] = a;
            d0[j]   = b - a;
        }
    }

    #pragma unroll 2
    for (int k = 0; k < 8; ++k) {
        const int row = rg * 8 + k;
        const float* xr = s_x + row * FEAT + lut * LUTK;
        const float b0 = xr[0], b1 = xr[1], b2 = xr[2];
        const float b3 = xr[3], b4 = xr[4], b5 = xr[5];

        float t[32];
        #pragma unroll
        for (int j = 0; j < 32; ++j) t[j] = fmaf(b0, d0[j], base[j]);
        #pragma unroll
        for (int j = 0; j < 16; ++j) t[j] = fmaf(b1, t[2*j+1] - t[2*j], t[2*j]);
        #pragma unroll
        for (int j = 0; j < 8;  ++j) t[j] = fmaf(b2, t[2*j+1] - t[2*j], t[2*j]);
        #pragma unroll
        for (int j = 0; j < 4;  ++j) t[j] = fmaf(b3, t[2*j+1] - t[2*j], t[2*j]);
        #pragma unroll
        for (int j = 0; j < 2;  ++j) t[j] = fmaf(b4, t[2*j+1] - t[2*j], t[2*j]);
        const float y = fmaf(b5, t[1] - t[0], t[0]);

        out[((size_t)row * OUTN + o) * LUTN + lut] = y;   // warp-coalesced 128B
    }
}

extern "C" void kernel_launch(void* const* d_in, const int* in_sizes, int n_in,
                              void* d_out, int out_size)
{
    const float* x = (const float*)d_in[0];   // [16,2,1024,384]
    const float* w = (const float*)d_in[1];   // [1024,64,64]
    float* out     = (float*)d_out;           // [16,2,1024,64]

    static bool attr_set = false;             // host-side only; eager API, capture-safe
    if (!attr_set) {
        cudaFuncSetAttribute(lut_tree_kernel,
                             cudaFuncAttributeMaxDynamicSharedMemorySize, SMEM_BYTES);
        attr_set = true;
    }
    lut_tree_kernel<<<OUTN, NTHREADS, SMEM_BYTES>>>(x, w, out);
}

// round 3
// speedup vs baseline: 1.1385x; 1.1385x over previous
#include <cuda_runtime.h>

// Problem constants
#define ROWS    32          // 16*2
#define OUTN    1024
#define LUTN    64
#define LUTK    6
#define ENT     64          // 1 << LUTK
#define FEAT    384         // LUTN * LUTK
#define WQ_PITCH 65         // odd stride -> conflict-free scalar LDS across luts

#define NTHREADS 256

__global__ __launch_bounds__(NTHREADS, 2)
void lut_tree_kernel(const float* __restrict__ x,
                     const float* __restrict__ w,
                     float* __restrict__ out)
{
    __shared__ float s_wq[LUTN * WQ_PITCH];   // 16.6 KB, static

    const int o   = blockIdx.x;               // output-feature index, 0..1023
    const int tid = threadIdx.x;

    // ---- Stage w[o], soft-quantize once: wq = (tanh(w)+1)/2 == sigmoid(2w) ----
    {
        const float4* wg = reinterpret_cast<const float4*>(w + (size_t)o * LUTN * ENT);
        #pragma unroll
        for (int i = tid; i < LUTN * ENT / 4; i += NTHREADS) {
            float4 v = wg[i];
            const int lut = i >> 4;
            const int e   = (i & 15) << 2;
            float* dst = s_wq + lut * WQ_PITCH + e;
            // sigmoid(2w) = 1/(1+exp(-2w)); __expf+__fdividef ~5 ops, ~1e-6 rel err
            dst[0] = __fdividef(1.0f, 1.0f + __expf(-2.0f * v.x));
            dst[1] = __fdividef(1.0f, 1.0f + __expf(-2.0f * v.y));
            dst[2] = __fdividef(1.0f, 1.0f + __expf(-2.0f * v.z));
            dst[3] = __fdividef(1.0f, 1.0f + __expf(-2.0f * v.w));
        }
    }
    __syncthreads();

    // ---- Thread = (lut, rowgroup). 64 luts x 4 rowgroups of 8 rows each. ----
    const int lut = tid & (LUTN - 1);
    const int rg  = tid >> 6;

    // Level-0 table in registers, hoisted across the 8 rows:
    // base[j] = wq[2j], d0[j] = wq[2j+1]-wq[2j]
    float base[32], d0[32];
    {
        const float* wqr = s_wq + lut * WQ_PITCH;
        #pragma unroll
        for (int j = 0; j < 32; ++j) {
            const float a = wqr[2 * j];
            const float b = wqr[2 * j + 1];
            base[j] = a;
            d0[j]   = b - a;
        }
    }

    // Bits straight from global (each x element is used by exactly one thread;
    // warp reads 768B contiguous per row; whole working set is L2-resident).
    const size_t row0   = (size_t)rg * 8;
    const float* xbase  = x + ((row0 * OUTN) + o) * FEAT + lut * LUTK;   // 8B aligned
    float*       obase  = out + ((row0 * OUTN) + o) * LUTN + lut;
    const size_t xstep  = (size_t)OUTN * FEAT;   // per-row stride in floats
    const size_t ostep  = (size_t)OUTN * LUTN;

    #pragma unroll
    for (int k = 0; k < 8; ++k) {
        const float2* xp = reinterpret_cast<const float2*>(xbase + k * xstep);
        const float2 p0 = xp[0];
        const float2 p1 = xp[1];
        const float2 p2 = xp[2];
        const float b0 = p0.x, b1 = p0.y, b2 = p1.x;
        const float b3 = p1.y, b4 = p2.x, b5 = p2.y;

        float t[32];
        #pragma unroll
        for (int j = 0; j < 32; ++j) t[j] = fmaf(b0, d0[j], base[j]);
        #pragma unroll
        for (int j = 0; j < 16; ++j) t[j] = fmaf(b1, t[2*j+1] - t[2*j], t[2*j]);
        #pragma unroll
        for (int j = 0; j < 8;  ++j) t[j] = fmaf(b2, t[2*j+1] - t[2*j], t[2*j]);
        #pragma unroll
        for (int j = 0; j < 4;  ++j) t[j] = fmaf(b3, t[2*j+1] - t[2*j], t[2*j]);
        #pragma unroll
        for (int j = 0; j < 2;  ++j) t[j] = fmaf(b4, t[2*j+1] - t[2*j], t[2*j]);
        const float y = fmaf(b5, t[1] - t[0], t[0]);

        obase[k * ostep] = y;   // warp-coalesced 128B per (warp,row)
    }
}

extern "C" void kernel_launch(void* const* d_in, const int* in_sizes, int n_in,
                              void* d_out, int out_size)
{
    const float* x = (const float*)d_in[0];   // [16,2,1024,384]
    const float* w = (const float*)d_in[1];   // [1024,64,64]
    float* out     = (float*)d_out;           // [16,2,1024,64]

    lut_tree_kernel<<<OUTN, NTHREADS>>>(x, w, out);
}